// round 1
// baseline (speedup 1.0000x reference)
#include <cuda_runtime.h>
#include <math_constants.h>

// Problem dims (fixed by dataset)
#define SS  128          // S
#define HH  8            // heads
#define QL  256          // Q (and K length)
#define DHD 32           // head dim
#define CC  256          // channels (= H*DH)
#define M_TOT (SS * QL)  // 32768 rows

// ---------------- scratch (device globals; no allocation allowed) ----------
__device__ float g_q[SS * HH * QL * DHD];   // [s,h,q,dh]
__device__ float g_k[SS * HH * QL * DHD];
__device__ float g_v[SS * HH * QL * DHD];
__device__ float g_g[M_TOT * CC];           // gate, [m, c]
__device__ float g_o[M_TOT * CC];           // attention out (gated), [m, c]

// ---------------- tiled fp32 GEMM: C[m,n] = sum_k X[m,k] * W[n,k] ----------
// X: [M,256] row-major, W: [256,256] row-major (out_features, in_features)
// MODE 0: write head-interleaved to [s,h,q,dh]
// MODE 1: sigmoid(c + bias[n]) -> out[m*256+n]
// MODE 2: c + bias[n]          -> out[m*256+n]
#define BM 64
#define BN 64
#define BK 16
#define SSTR 72   // padded row stride (16B-aligned float4 reads, fewer STS conflicts)

template <int MODE>
__global__ __launch_bounds__(256) void gemm_k(const float* __restrict__ X,
                                              const float* __restrict__ W,
                                              const float* __restrict__ bias,
                                              float* __restrict__ out) {
    __shared__ float As[BK][SSTR];
    __shared__ float Bs[BK][SSTR];
    const int bm = blockIdx.y * BM;
    const int bn = blockIdx.x * BN;
    const int tid = threadIdx.x;
    const int lr = tid >> 2;           // 0..63 row in tile
    const int lc = (tid & 3) << 2;     // 0,4,8,12 k offset
    const int tm = (tid >> 4) << 2;    // 0..60
    const int tn = (tid & 15) << 2;    // 0..60

    float acc[4][4] = {};
    const float* xp = X + (bm + lr) * CC + lc;
    const float* wp = W + (bn + lr) * CC + lc;

    for (int k0 = 0; k0 < CC; k0 += BK) {
        float4 a = *(const float4*)(xp + k0);
        float4 b = *(const float4*)(wp + k0);
        As[lc + 0][lr] = a.x; As[lc + 1][lr] = a.y;
        As[lc + 2][lr] = a.z; As[lc + 3][lr] = a.w;
        Bs[lc + 0][lr] = b.x; Bs[lc + 1][lr] = b.y;
        Bs[lc + 2][lr] = b.z; Bs[lc + 3][lr] = b.w;
        __syncthreads();
#pragma unroll
        for (int kk = 0; kk < BK; kk++) {
            float4 ra = *(const float4*)&As[kk][tm];
            float4 rb = *(const float4*)&Bs[kk][tn];
            float va[4] = {ra.x, ra.y, ra.z, ra.w};
            float vb[4] = {rb.x, rb.y, rb.z, rb.w};
#pragma unroll
            for (int i = 0; i < 4; i++)
#pragma unroll
                for (int j = 0; j < 4; j++)
                    acc[i][j] = fmaf(va[i], vb[j], acc[i][j]);
        }
        __syncthreads();
    }

#pragma unroll
    for (int i = 0; i < 4; i++) {
        const int m = bm + tm + i;
#pragma unroll
        for (int j = 0; j < 4; j++) {
            const int n = bn + tn + j;
            float c = acc[i][j];
            if (MODE == 1) c = 1.0f / (1.0f + __expf(-(c + bias[n])));
            if (MODE == 2) c = c + bias[n];
            if (MODE == 0) {
                const int s = m >> 8, q = m & 255, h = n >> 5, dh = n & 31;
                out[(((s * HH + h) * QL) + q) * DHD + dh] = c;
            } else {
                out[m * CC + n] = c;
            }
        }
    }
}

// ---------------- attention: one CTA per (s,h), one query row per thread ---
// scores = q.k + bias_mask[s,k] + bias_pair[h,q,k]; online softmax; o = a.v
// gate applied at write: o[m, h*32+dh] *= g[m, h*32+dh]
__global__ __launch_bounds__(256) void attn_k(const float* __restrict__ qb,
                                              const float* __restrict__ kb,
                                              const float* __restrict__ vb,
                                              const float* __restrict__ bias_mask,
                                              const float* __restrict__ bias_pair,
                                              const float* __restrict__ gbuf,
                                              float* __restrict__ obuf) {
    extern __shared__ float sm[];
    float* Ks = sm;               // 256*32
    float* Vs = sm + QL * DHD;    // 256*32
    float* bms = sm + 2 * QL * DHD;  // 256

    const int sh = blockIdx.x;
    const int s = sh >> 3, h = sh & 7;
    const int tid = threadIdx.x;  // = query row

    const float* kp = kb + sh * (QL * DHD);
    const float* vp = vb + sh * (QL * DHD);
    for (int i = tid * 4; i < QL * DHD; i += 1024) {
        *(float4*)(Ks + i) = *(const float4*)(kp + i);
        *(float4*)(Vs + i) = *(const float4*)(vp + i);
    }
    bms[tid] = bias_mask[s * QL + tid];
    __syncthreads();

    float qr[DHD];
    const float* qp = qb + (sh * QL + tid) * DHD;
#pragma unroll
    for (int d = 0; d < DHD; d += 4) {
        float4 t = *(const float4*)(qp + d);
        qr[d] = t.x; qr[d + 1] = t.y; qr[d + 2] = t.z; qr[d + 3] = t.w;
    }
    const float* bp = bias_pair + (h * QL + tid) * QL;

    float mrun = -CUDART_INF_F, lrun = 0.0f;
    float acc[DHD];
#pragma unroll
    for (int d = 0; d < DHD; d++) acc[d] = 0.0f;

    for (int kt = 0; kt < QL; kt += 32) {
        float sc[32];
#pragma unroll
        for (int kk = 0; kk < 32; kk++) {
            float sum = bms[kt + kk] + bp[kt + kk];
            const float* kr = Ks + (kt + kk) * DHD;
#pragma unroll
            for (int d = 0; d < DHD; d += 4) {
                float4 kv = *(const float4*)(kr + d);
                sum = fmaf(qr[d],     kv.x, sum);
                sum = fmaf(qr[d + 1], kv.y, sum);
                sum = fmaf(qr[d + 2], kv.z, sum);
                sum = fmaf(qr[d + 3], kv.w, sum);
            }
            sc[kk] = sum;
        }
        float tmax = mrun;
#pragma unroll
        for (int kk = 0; kk < 32; kk++) tmax = fmaxf(tmax, sc[kk]);
        const float rescale = __expf(mrun - tmax);  // exp(-inf)=0 on first tile
        lrun *= rescale;
#pragma unroll
        for (int d = 0; d < DHD; d++) acc[d] *= rescale;
#pragma unroll
        for (int kk = 0; kk < 32; kk++) {
            const float w = __expf(sc[kk] - tmax);
            lrun += w;
            const float* vr = Vs + (kt + kk) * DHD;
#pragma unroll
            for (int d = 0; d < DHD; d += 4) {
                float4 vv = *(const float4*)(vr + d);
                acc[d]     = fmaf(w, vv.x, acc[d]);
                acc[d + 1] = fmaf(w, vv.y, acc[d + 1]);
                acc[d + 2] = fmaf(w, vv.z, acc[d + 2]);
                acc[d + 3] = fmaf(w, vv.w, acc[d + 3]);
            }
        }
        mrun = tmax;
    }

    const float inv = 1.0f / lrun;
    const int mrow = s * QL + tid;
    const float* gp = gbuf + mrow * CC + h * DHD;
    float* op = obuf + mrow * CC + h * DHD;
#pragma unroll
    for (int d = 0; d < DHD; d += 4) {
        float4 gg = *(const float4*)(gp + d);
        float4 ov;
        ov.x = acc[d]     * inv * gg.x;
        ov.y = acc[d + 1] * inv * gg.y;
        ov.z = acc[d + 2] * inv * gg.z;
        ov.w = acc[d + 3] * inv * gg.w;
        *(float4*)(op + d) = ov;
    }
}

// ---------------- launch ---------------------------------------------------
extern "C" void kernel_launch(void* const* d_in, const int* in_sizes, int n_in,
                              void* d_out, int out_size) {
    const float* q_x       = (const float*)d_in[0];
    const float* kv_x      = (const float*)d_in[1];
    const float* bias_mask = (const float*)d_in[2];
    const float* bias_pair = (const float*)d_in[3];
    const float* Wq        = (const float*)d_in[4];
    const float* Wk        = (const float*)d_in[5];
    const float* Wv        = (const float*)d_in[6];
    const float* Wg        = (const float*)d_in[7];
    const float* bg        = (const float*)d_in[8];
    const float* Wo        = (const float*)d_in[9];
    const float* bo        = (const float*)d_in[10];
    float* out = (float*)d_out;

    float *qb, *kb, *vb, *gb, *ob;
    cudaGetSymbolAddress((void**)&qb, g_q);
    cudaGetSymbolAddress((void**)&kb, g_k);
    cudaGetSymbolAddress((void**)&vb, g_v);
    cudaGetSymbolAddress((void**)&gb, g_g);
    cudaGetSymbolAddress((void**)&ob, g_o);

    const dim3 grid(CC / BN, M_TOT / BM);  // (4, 512)

    gemm_k<0><<<grid, 256>>>(q_x,  Wq, nullptr, qb);
    gemm_k<0><<<grid, 256>>>(kv_x, Wk, nullptr, kb);
    gemm_k<0><<<grid, 256>>>(kv_x, Wv, nullptr, vb);
    gemm_k<1><<<grid, 256>>>(q_x,  Wg, bg,      gb);

    const int smem_bytes = (2 * QL * DHD + QL) * (int)sizeof(float);  // 66.5 KB
    cudaFuncSetAttribute(attn_k, cudaFuncAttributeMaxDynamicSharedMemorySize,
                         smem_bytes);
    attn_k<<<SS * HH, 256, smem_bytes>>>(qb, kb, vb, bias_mask, bias_pair, gb, ob);

    gemm_k<2><<<grid, 256>>>(ob, Wo, bo, out);
}